// round 1
// baseline (speedup 1.0000x reference)
#include <cuda_runtime.h>
#include <math.h>

#define NPIX 65536
#define HDIM 256
#define WDIM 256
#define NB   8

// ---------------- scratch (device globals; no allocation allowed) ----------------
__device__ float g_q [(size_t)NB * 64 * NPIX];   // (b, 64ch, n)   channel-major
__device__ float g_v [(size_t)NB * NPIX * 32];   // (b, n, 32ch)   pixel-major
__device__ float g_ek[(size_t)NB * 16 * NPIX];   // (b, 16ch, n)   exp(k logits)
__device__ float g_sumexp[NB * 16];
__device__ float g_cross [NB * 16 * 32];
__device__ float g_lamc  [NB * 16 * 32];

// ---------------- zero accumulators ----------------
__global__ void zero_kernel() {
    int t = threadIdx.x;
    for (int i = t; i < NB * 16 * 32; i += 256) g_cross[i] = 0.f;
    if (t < NB * 16) g_sumexp[t] = 0.f;
}

// ---------------- q projection: q = BN(Wq x) -> g_q ----------------
// block: 256 threads = 4 out-groups x 64 pixel-groups; 256 pixels per block
__global__ void qproj_kernel(const float* __restrict__ x,
                             const float* __restrict__ Wq,
                             const float* __restrict__ gq,
                             const float* __restrict__ bq) {
    __shared__ float w_sh[64 * 64];
    __shared__ float x_sh[16 * 256];
    const int t = threadIdx.x;
    const int b = blockIdx.y;
    const int pbase = blockIdx.x * 256;

    const float inv = rsqrtf(1.0f + 1e-5f);
    for (int i = t; i < 4096; i += 256) {
        int o = i >> 6;
        w_sh[i] = Wq[i] * gq[o] * inv;      // fold BN scale
    }

    const int og = t >> 6;       // 0..3  (16 outputs each)
    const int pg = t & 63;       // 4 pixels each

    float a[64];
#pragma unroll
    for (int i = 0; i < 64; i++) a[i] = 0.f;

    const float* xb = x + ((size_t)b * 64) * NPIX + pbase;

#pragma unroll 1
    for (int c0 = 0; c0 < 64; c0 += 16) {
        __syncthreads();
        for (int i = t; i < 1024; i += 256) {
            int cc = i >> 6, p4 = i & 63;
            ((float4*)x_sh)[i] = *(const float4*)(xb + (size_t)(c0 + cc) * NPIX + p4 * 4);
        }
        __syncthreads();
#pragma unroll
        for (int cc = 0; cc < 16; cc++) {
            float4 xv = ((float4*)x_sh)[cc * 64 + pg];
            const float* wr = w_sh + (og * 16) * 64 + c0 + cc;
#pragma unroll
            for (int o = 0; o < 16; o++) {
                float w = wr[o * 64];
                a[o*4+0] += w * xv.x;
                a[o*4+1] += w * xv.y;
                a[o*4+2] += w * xv.z;
                a[o*4+3] += w * xv.w;
            }
        }
    }
    float* qb = g_q + ((size_t)b * 64 + og * 16) * NPIX + pbase + pg * 4;
#pragma unroll
    for (int o = 0; o < 16; o++) {
        float bb = bq[og * 16 + o];
        float4 s = make_float4(a[o*4+0] + bb, a[o*4+1] + bb, a[o*4+2] + bb, a[o*4+3] + bb);
        *(float4*)(qb + (size_t)o * NPIX) = s;
    }
}

// ---------------- k/v projection: ek = exp(Wk x), v = BN(Wv x), + sumexp ----------------
// block: 192 threads = 3 out-groups (k0-15, v0-15, v16-31) x 64 pixel-groups
__global__ void kvproj_kernel(const float* __restrict__ x,
                              const float* __restrict__ Wk,
                              const float* __restrict__ Wv,
                              const float* __restrict__ gv,
                              const float* __restrict__ bv) {
    __shared__ float w_sh[48 * 64];
    __shared__ float x_sh[16 * 256];
    const int t = threadIdx.x;
    const int b = blockIdx.y;
    const int pbase = blockIdx.x * 256;

    const float inv = rsqrtf(1.0f + 1e-5f);
    for (int i = t; i < 3072; i += 192) {
        int o = i >> 6, c = i & 63;
        if (o < 16) w_sh[i] = Wk[o * 64 + c];
        else { int vo = o - 16; w_sh[i] = Wv[vo * 64 + c] * gv[vo] * inv; }
    }

    const int og = t >> 6;       // 0..2
    const int pg = t & 63;

    float a[64];
#pragma unroll
    for (int i = 0; i < 64; i++) a[i] = 0.f;

    const float* xb = x + ((size_t)b * 64) * NPIX + pbase;

#pragma unroll 1
    for (int c0 = 0; c0 < 64; c0 += 16) {
        __syncthreads();
        for (int i = t; i < 1024; i += 192) {
            int cc = i >> 6, p4 = i & 63;
            ((float4*)x_sh)[i] = *(const float4*)(xb + (size_t)(c0 + cc) * NPIX + p4 * 4);
        }
        __syncthreads();
#pragma unroll
        for (int cc = 0; cc < 16; cc++) {
            float4 xv = ((float4*)x_sh)[cc * 64 + pg];
            const float* wr = w_sh + (og * 16) * 64 + c0 + cc;
#pragma unroll
            for (int o = 0; o < 16; o++) {
                float w = wr[o * 64];
                a[o*4+0] += w * xv.x;
                a[o*4+1] += w * xv.y;
                a[o*4+2] += w * xv.z;
                a[o*4+3] += w * xv.w;
            }
        }
    }

    if (og == 0) {
        // exp, store ek, reduce sumexp
        float ps[16];
#pragma unroll
        for (int o = 0; o < 16; o++) {
            float e0 = __expf(a[o*4+0]);
            float e1 = __expf(a[o*4+1]);
            float e2 = __expf(a[o*4+2]);
            float e3 = __expf(a[o*4+3]);
            ps[o] = e0 + e1 + e2 + e3;
            float4 s = make_float4(e0, e1, e2, e3);
            *(float4*)(g_ek + ((size_t)b * 16 + o) * NPIX + pbase + pg * 4) = s;
        }
#pragma unroll
        for (int off = 16; off > 0; off >>= 1)
#pragma unroll
            for (int o = 0; o < 16; o++)
                ps[o] += __shfl_xor_sync(0xffffffffu, ps[o], off);
        if ((t & 31) == 0) {
#pragma unroll
            for (int o = 0; o < 16; o++)
                atomicAdd(&g_sumexp[b * 16 + o], ps[o]);
        }
    } else {
        const int vb = (og - 1) * 16;
        float bvv[16];
#pragma unroll
        for (int o = 0; o < 16; o++) bvv[o] = bv[vb + o];
#pragma unroll
        for (int j = 0; j < 4; j++) {
            float* dst = g_v + ((size_t)b * NPIX + pbase + pg * 4 + j) * 32 + vb;
#pragma unroll
            for (int o4 = 0; o4 < 4; o4++) {
                float4 s = make_float4(a[(o4*4+0)*4 + j] + bvv[o4*4+0],
                                       a[(o4*4+1)*4 + j] + bvv[o4*4+1],
                                       a[(o4*4+2)*4 + j] + bvv[o4*4+2],
                                       a[(o4*4+3)*4 + j] + bvv[o4*4+3]);
                *(float4*)(dst + o4 * 4) = s;
            }
        }
    }
}

// ---------------- content lambda: cross[b,k,v] = sum_n ek[k,n] v[v,n] ----------------
// grid (32, 8); block 512 threads = (k 16) x (v 32); each block covers 2048 pixels
__global__ void cross_kernel() {
    __shared__ float ek_sh[16 * 128];
    __shared__ float v_sh[128 * 32];
    const int t = threadIdx.x;
    const int b = blockIdx.y;
    const int base0 = blockIdx.x * 2048;
    const int k = t >> 5, v = t & 31;
    float c = 0.f;
#pragma unroll 1
    for (int ch = 0; ch < 16; ch++) {
        int pb = base0 + ch * 128;
        __syncthreads();
        {
            int kk = t >> 5, p4 = t & 31;
            ((float4*)ek_sh)[t] = *(const float4*)(g_ek + ((size_t)b * 16 + kk) * NPIX + pb + p4 * 4);
        }
        for (int i = t; i < 1024; i += 512) {
            ((float4*)v_sh)[i] = *(const float4*)(g_v + ((size_t)b * NPIX + pb) * 32 + i * 4);
        }
        __syncthreads();
#pragma unroll 8
        for (int p = 0; p < 128; p++)
            c += ek_sh[k * 128 + p] * v_sh[p * 32 + v];
    }
    atomicAdd(&g_cross[b * 512 + k * 32 + v], c);
}

// ---------------- finalize: lamc' = cross / sumexp + bp[k] ----------------
__global__ void finalize_kernel(const float* __restrict__ bp) {
    const int t = threadIdx.x;          // 512
    const int k = t >> 5;
    for (int b = 0; b < NB; b++)
        g_lamc[b * 512 + t] = g_cross[b * 512 + t] / g_sumexp[b * 16 + k] + bp[k];
}

// ---------------- output: Y[h,v,n] = sum_k q*lamc' + sum_s r[s]*v[n+s] ----------------
// grid (4, 128, 8); block 256 = (4 heads) x (64 pixel-x); tile 64x2 pixels, halo 66x4
__global__ void out_kernel(const float* __restrict__ Wp, float* __restrict__ out) {
    __shared__ float vt[4 * 66 * 36];     // padded stride 36 -> conflict-free LDS.128
    __shared__ float lamc_sh[512];
    __shared__ float wp_sh[144];
    const int t = threadIdx.x;
    const int b = blockIdx.z;
    const int gx = blockIdx.x * 64;
    const int gy = blockIdx.y * 2;

    for (int i = t; i < 2112; i += 256) {          // 4 rows * 66 x * 8 float4
        int ry = i / 528; int r2 = i - ry * 528;
        int lx = r2 >> 3;  int c4 = r2 & 7;
        int y = gy - 1 + ry, xx = gx - 1 + lx;
        float4 val = make_float4(0.f, 0.f, 0.f, 0.f);
        if (y >= 0 && y < HDIM && xx >= 0 && xx < WDIM)
            val = *(const float4*)(g_v + ((size_t)b * NPIX + y * WDIM + xx) * 32 + c4 * 4);
        *(float4*)(vt + (ry * 66 + lx) * 36 + c4 * 4) = val;
    }
    for (int i = t; i < 512; i += 256) lamc_sh[i] = g_lamc[b * 512 + i];
    if (t < 144) wp_sh[t] = Wp[t];
    __syncthreads();

    const int hd = t >> 6, pg = t & 63;

#pragma unroll 1
    for (int ty = 0; ty < 2; ty++) {
        const int pix = (gy + ty) * WDIM + gx + pg;
        float q[16];
#pragma unroll
        for (int kk = 0; kk < 16; kk++)
            q[kk] = g_q[((size_t)b * 64 + hd * 16 + kk) * NPIX + pix];

        float r[9];
#pragma unroll
        for (int s = 0; s < 9; s++) {
            float rv = 0.f;
#pragma unroll
            for (int kk = 0; kk < 16; kk++) rv += q[kk] * wp_sh[kk * 9 + s];
            r[s] = rv;
        }

        float acc[32];
#pragma unroll
        for (int v = 0; v < 32; v++) acc[v] = 0.f;

        // content term (lamc' includes bp fold)
#pragma unroll
        for (int kk = 0; kk < 16; kk++) {
            float qk = q[kk];
#pragma unroll
            for (int v4 = 0; v4 < 8; v4++) {
                float4 lc = *(const float4*)(lamc_sh + kk * 32 + v4 * 4);
                acc[4*v4+0] += qk * lc.x;
                acc[4*v4+1] += qk * lc.y;
                acc[4*v4+2] += qk * lc.z;
                acc[4*v4+3] += qk * lc.w;
            }
        }
        // position term: r applied to raw v neighborhood (conv folded into r)
#pragma unroll
        for (int dy = 0; dy < 3; dy++) {
#pragma unroll
            for (int dx = 0; dx < 3; dx++) {
                float rs = r[dy * 3 + dx];
                const float* vp = vt + ((ty + dy) * 66 + pg + dx) * 36;
#pragma unroll
                for (int v4 = 0; v4 < 8; v4++) {
                    float4 vv = *(const float4*)(vp + v4 * 4);
                    acc[4*v4+0] += rs * vv.x;
                    acc[4*v4+1] += rs * vv.y;
                    acc[4*v4+2] += rs * vv.z;
                    acc[4*v4+3] += rs * vv.w;
                }
            }
        }
        float* ob = out + ((size_t)b * 128 + hd * 32) * NPIX + pix;
#pragma unroll
        for (int v = 0; v < 32; v++) ob[(size_t)v * NPIX] = acc[v];
    }
}

// ---------------- launch ----------------
extern "C" void kernel_launch(void* const* d_in, const int* in_sizes, int n_in,
                              void* d_out, int out_size) {
    const float* x  = (const float*)d_in[0];
    const float* Wq = (const float*)d_in[1];
    const float* gq = (const float*)d_in[2];
    const float* bq = (const float*)d_in[3];
    const float* Wk = (const float*)d_in[4];
    const float* Wv = (const float*)d_in[5];
    const float* gv = (const float*)d_in[6];
    const float* bv = (const float*)d_in[7];
    const float* Wp = (const float*)d_in[8];
    const float* bp = (const float*)d_in[9];
    float* out = (float*)d_out;

    zero_kernel<<<1, 256>>>();
    qproj_kernel<<<dim3(NPIX / 256, NB), 256>>>(x, Wq, gq, bq);
    kvproj_kernel<<<dim3(NPIX / 256, NB), 192>>>(x, Wk, Wv, gv, bv);
    cross_kernel<<<dim3(32, NB), 512>>>();
    finalize_kernel<<<1, 512>>>(bp);
    out_kernel<<<dim3(4, 128, NB), 256>>>(Wp, out);
}

// round 2
// speedup vs baseline: 1.9995x; 1.9995x over previous
#include <cuda_runtime.h>
#include <math.h>

#define NPIX 65536
#define NB   8

typedef unsigned long long ull;

__device__ __forceinline__ void ffma2(ull &d, ull a, ull b) {
    asm("fma.rn.f32x2 %0, %1, %2, %0;" : "+l"(d) : "l"(a), "l"(b));
}
__device__ __forceinline__ ull dup2(float x) {
    ull r; unsigned xi = __float_as_uint(x);
    asm("mov.b64 %0, {%1, %1};" : "=l"(r) : "r"(xi));
    return r;
}
__device__ __forceinline__ float2 unpk(ull d) {
    unsigned lo, hi;
    asm("mov.b64 {%0, %1}, %2;" : "=r"(lo), "=r"(hi) : "l"(d));
    return make_float2(__uint_as_float(lo), __uint_as_float(hi));
}

// ---------------- scratch ----------------
__device__ float g_q [(size_t)NB * 64 * NPIX];   // (b, 64ch, n)  channel-major
__device__ float g_vc[(size_t)NB * 32 * NPIX];   // (b, 32ch, n)  channel-major
__device__ float g_ek[(size_t)NB * 16 * NPIX];   // (b, 16ch, n)
__device__ float g_sumexp[NB * 16];
__device__ float g_cross [NB * 16 * 32];
__device__ float g_lamc  [NB * 16 * 32];

__global__ void zero_kernel() {
    int t = threadIdx.x;
    for (int i = t; i < NB * 16 * 32; i += 256) g_cross[i] = 0.f;
    if (t < NB * 16) g_sumexp[t] = 0.f;
}

// ---------------- q projection (f32x2 microkernel) ----------------
__global__ void qproj_kernel(const float* __restrict__ x,
                             const float* __restrict__ Wq,
                             const float* __restrict__ gq,
                             const float* __restrict__ bq) {
    __shared__ float w_sh[64 * 66];      // [c][o], pad 66
    __shared__ float x_sh[16 * 256];
    const int t = threadIdx.x;
    const int b = blockIdx.y;
    const int pbase = blockIdx.x * 256;

    const float inv = rsqrtf(1.0f + 1e-5f);
    for (int i = t; i < 4096; i += 256) {
        int o = i >> 6, c = i & 63;
        w_sh[c * 66 + o] = Wq[i] * gq[o] * inv;
    }

    const int og = t >> 6;       // 0..3
    const int pg = t & 63;       // 4 pixels

    ull acc2[32];
#pragma unroll
    for (int i = 0; i < 32; i++) acc2[i] = 0ull;

    const float* xb = x + ((size_t)b * 64) * NPIX + pbase;

#pragma unroll 1
    for (int c0 = 0; c0 < 64; c0 += 16) {
        __syncthreads();
        for (int i = t; i < 1024; i += 256) {
            int cc = i >> 6, p4 = i & 63;
            ((float4*)x_sh)[i] = *(const float4*)(xb + (size_t)(c0 + cc) * NPIX + p4 * 4);
        }
        __syncthreads();
#pragma unroll
        for (int cc = 0; cc < 16; cc++) {
            float4 xv = ((float4*)x_sh)[cc * 64 + pg];
            ull bx = dup2(xv.x), by = dup2(xv.y), bz = dup2(xv.z), bw = dup2(xv.w);
            const float* wr = w_sh + (c0 + cc) * 66 + og * 16;
#pragma unroll
            for (int p = 0; p < 8; p++) {
                ull wp2 = *(const ull*)(wr + 2 * p);
                ffma2(acc2[p*4+0], wp2, bx);
                ffma2(acc2[p*4+1], wp2, by);
                ffma2(acc2[p*4+2], wp2, bz);
                ffma2(acc2[p*4+3], wp2, bw);
            }
        }
    }
    float* qb = g_q + ((size_t)b * 64 + og * 16) * NPIX + pbase + pg * 4;
#pragma unroll
    for (int p = 0; p < 8; p++) {
        float2 j0 = unpk(acc2[p*4+0]), j1 = unpk(acc2[p*4+1]);
        float2 j2 = unpk(acc2[p*4+2]), j3 = unpk(acc2[p*4+3]);
        float blo = bq[og * 16 + 2*p], bhi = bq[og * 16 + 2*p + 1];
        *(float4*)(qb + (size_t)(2*p)   * NPIX) = make_float4(j0.x+blo, j1.x+blo, j2.x+blo, j3.x+blo);
        *(float4*)(qb + (size_t)(2*p+1) * NPIX) = make_float4(j0.y+bhi, j1.y+bhi, j2.y+bhi, j3.y+bhi);
    }
}

// ---------------- k/v projection: ek + v (channel-major store) ----------------
__global__ void kvproj_kernel(const float* __restrict__ x,
                              const float* __restrict__ Wk,
                              const float* __restrict__ Wv,
                              const float* __restrict__ gv,
                              const float* __restrict__ bv) {
    __shared__ float w_sh[64 * 50];      // [c][o], 48 outs pad 50
    __shared__ float x_sh[16 * 256];
    const int t = threadIdx.x;
    const int b = blockIdx.y;
    const int pbase = blockIdx.x * 256;

    const float inv = rsqrtf(1.0f + 1e-5f);
    for (int i = t; i < 3072; i += 192) {
        int o = i >> 6, c = i & 63;
        float val;
        if (o < 16) val = Wk[o * 64 + c];
        else { int vo = o - 16; val = Wv[vo * 64 + c] * gv[vo] * inv; }
        w_sh[c * 50 + o] = val;
    }

    const int og = t >> 6;       // 0..2
    const int pg = t & 63;

    ull acc2[32];
#pragma unroll
    for (int i = 0; i < 32; i++) acc2[i] = 0ull;

    const float* xb = x + ((size_t)b * 64) * NPIX + pbase;

#pragma unroll 1
    for (int c0 = 0; c0 < 64; c0 += 16) {
        __syncthreads();
        for (int i = t; i < 1024; i += 192) {
            int cc = i >> 6, p4 = i & 63;
            ((float4*)x_sh)[i] = *(const float4*)(xb + (size_t)(c0 + cc) * NPIX + p4 * 4);
        }
        __syncthreads();
#pragma unroll
        for (int cc = 0; cc < 16; cc++) {
            float4 xv = ((float4*)x_sh)[cc * 64 + pg];
            ull bx = dup2(xv.x), by = dup2(xv.y), bz = dup2(xv.z), bw = dup2(xv.w);
            const float* wr = w_sh + (c0 + cc) * 50 + og * 16;
#pragma unroll
            for (int p = 0; p < 8; p++) {
                ull wp2 = *(const ull*)(wr + 2 * p);
                ffma2(acc2[p*4+0], wp2, bx);
                ffma2(acc2[p*4+1], wp2, by);
                ffma2(acc2[p*4+2], wp2, bz);
                ffma2(acc2[p*4+3], wp2, bw);
            }
        }
    }

    if (og == 0) {
        float ps[16];
#pragma unroll
        for (int p = 0; p < 8; p++) {
            float2 j0 = unpk(acc2[p*4+0]), j1 = unpk(acc2[p*4+1]);
            float2 j2 = unpk(acc2[p*4+2]), j3 = unpk(acc2[p*4+3]);
            float e0 = __expf(j0.x), e1 = __expf(j1.x), e2 = __expf(j2.x), e3 = __expf(j3.x);
            ps[2*p] = e0 + e1 + e2 + e3;
            *(float4*)(g_ek + ((size_t)b * 16 + 2*p) * NPIX + pbase + pg * 4) = make_float4(e0, e1, e2, e3);
            float f0 = __expf(j0.y), f1 = __expf(j1.y), f2 = __expf(j2.y), f3 = __expf(j3.y);
            ps[2*p+1] = f0 + f1 + f2 + f3;
            *(float4*)(g_ek + ((size_t)b * 16 + 2*p+1) * NPIX + pbase + pg * 4) = make_float4(f0, f1, f2, f3);
        }
#pragma unroll
        for (int off = 16; off > 0; off >>= 1)
#pragma unroll
            for (int o = 0; o < 16; o++)
                ps[o] += __shfl_xor_sync(0xffffffffu, ps[o], off);
        if ((t & 31) == 0) {
#pragma unroll
            for (int o = 0; o < 16; o++)
                atomicAdd(&g_sumexp[b * 16 + o], ps[o]);
        }
    } else {
        const int vb = (og - 1) * 16;
#pragma unroll
        for (int p = 0; p < 8; p++) {
            float2 j0 = unpk(acc2[p*4+0]), j1 = unpk(acc2[p*4+1]);
            float2 j2 = unpk(acc2[p*4+2]), j3 = unpk(acc2[p*4+3]);
            float blo = bv[vb + 2*p], bhi = bv[vb + 2*p + 1];
            *(float4*)(g_vc + ((size_t)b * 32 + vb + 2*p)   * NPIX + pbase + pg * 4)
                = make_float4(j0.x+blo, j1.x+blo, j2.x+blo, j3.x+blo);
            *(float4*)(g_vc + ((size_t)b * 32 + vb + 2*p+1) * NPIX + pbase + pg * 4)
                = make_float4(j0.y+bhi, j1.y+bhi, j2.y+bhi, j3.y+bhi);
        }
    }
}

// ---------------- content lambda: cross[b,k,v] = sum_n ek[k,n] v[v,n] ----------------
// 512 threads = k(16) x vhalf(2) x vpair(16); tile 128 px, smem transpose of v
__global__ void cross_kernel() {
    __shared__ float ek_sh[16 * 128];
    __shared__ float v_sh[128 * 34];       // [p][v], pad 34
    const int t = threadIdx.x;
    const int b = blockIdx.y;
    const int base0 = blockIdx.x * 2048;
    const int k = t >> 5, vh = (t >> 4) & 1, v2 = t & 15;

    ull c2 = 0ull;
#pragma unroll 1
    for (int ch = 0; ch < 16; ch++) {
        int pb = base0 + ch * 128;
        __syncthreads();
        {
            int kk = t >> 5, p4 = t & 31;
            ((float4*)ek_sh)[t] = *(const float4*)(g_ek + ((size_t)b * 16 + kk) * NPIX + pb + p4 * 4);
        }
        for (int i = t; i < 1024; i += 512) {
            int c = i >> 5, p4 = i & 31;
            float4 f = *(const float4*)(g_vc + ((size_t)b * 32 + c) * NPIX + pb + p4 * 4);
            v_sh[(p4*4+0) * 34 + c] = f.x;
            v_sh[(p4*4+1) * 34 + c] = f.y;
            v_sh[(p4*4+2) * 34 + c] = f.z;
            v_sh[(p4*4+3) * 34 + c] = f.w;
        }
        __syncthreads();
        const int pl = vh * 64;
#pragma unroll 8
        for (int p = 0; p < 64; p++) {
            ull ekd = dup2(ek_sh[k * 128 + pl + p]);
            ull vv = *(const ull*)(v_sh + (pl + p) * 34 + 2 * v2);
            ffma2(c2, vv, ekd);
        }
    }
    float2 r = unpk(c2);
    atomicAdd(&g_cross[b * 512 + k * 32 + 2*v2],     r.x);
    atomicAdd(&g_cross[b * 512 + k * 32 + 2*v2 + 1], r.y);
}

// ---------------- finalize ----------------
__global__ void finalize_kernel(const float* __restrict__ bp) {
    const int t = threadIdx.x;          // 512
    const int k = t >> 5;
    for (int b = 0; b < NB; b++)
        g_lamc[b * 512 + t] = g_cross[b * 512 + t] / g_sumexp[b * 16 + k] + bp[k];
}

// ---------------- output ----------------
// 128 threads = 4 heads x 2 v-halves x 16 pixel-slots; 4 strided px per thread
__global__ void __launch_bounds__(128) out_kernel(const float* __restrict__ Wp,
                                                  float* __restrict__ out) {
    __shared__ float vt[4 * 66 * 36];    // pixel-major halo, stride 36
    __shared__ float q_sh[64 * 68];      // [ch][px], pad 68
    __shared__ float lamc_sh[512];
    __shared__ float wp_sh[144];
    const int t = threadIdx.x;
    const int b = blockIdx.z;
    const int gx = blockIdx.x * 64;
    const int gy = blockIdx.y * 2;

    // halo: channel-major gmem -> pixel-major smem
    for (int i = t; i < 8448; i += 128) {
        int c = i / 264;
        int xi = i - c * 264;
        int row = xi / 66;
        int x = xi - row * 66;
        int y = gy - 1 + row, xx = gx - 1 + x;
        float val = 0.f;
        if ((unsigned)y < 256u && (unsigned)xx < 256u)
            val = g_vc[((size_t)b * 32 + c) * NPIX + y * 256 + xx];
        vt[(row * 66 + x) * 36 + c] = val;
    }
    for (int i = t; i < 512; i += 128) lamc_sh[i] = g_lamc[b * 512 + i];
    for (int i = t; i < 144; i += 128) wp_sh[i] = Wp[i];

    const int pxg = t & 15, vh = (t >> 4) & 1, hd = t >> 5;

#pragma unroll 1
    for (int ty = 0; ty < 2; ty++) {
        __syncthreads();
        // stage q for this row
        const float* qsrc = g_q + ((size_t)b * 64) * NPIX + (gy + ty) * 256 + gx;
        for (int i = t; i < 1024; i += 128) {
            int ch = i >> 4, p4 = i & 15;
            *(float4*)(q_sh + ch * 68 + p4 * 4) = *(const float4*)(qsrc + (size_t)ch * NPIX + p4 * 4);
        }
        __syncthreads();

        // r per pixel-slot
        float r[4][9];
#pragma unroll
        for (int s = 0; s < 4; s++) {
            int px = pxg + s * 16;
            float qv[16];
#pragma unroll
            for (int kk = 0; kk < 16; kk++) qv[kk] = q_sh[(hd * 16 + kk) * 68 + px];
#pragma unroll
            for (int j = 0; j < 9; j++) {
                float rv = 0.f;
#pragma unroll
                for (int kk = 0; kk < 16; kk++) rv += qv[kk] * wp_sh[kk * 9 + j];
                r[s][j] = rv;
            }
        }

        ull acc2[4][8];
#pragma unroll
        for (int s = 0; s < 4; s++)
#pragma unroll
            for (int p = 0; p < 8; p++) acc2[s][p] = 0ull;

        // content term
        const float* lamb = lamc_sh + vh * 16;
#pragma unroll
        for (int kk = 0; kk < 16; kk++) {
            ulonglong2 l0 = *(const ulonglong2*)(lamb + kk * 32);
            ulonglong2 l1 = *(const ulonglong2*)(lamb + kk * 32 + 4);
            ulonglong2 l2 = *(const ulonglong2*)(lamb + kk * 32 + 8);
            ulonglong2 l3 = *(const ulonglong2*)(lamb + kk * 32 + 12);
            const float* qrow = q_sh + (hd * 16 + kk) * 68 + pxg;
#pragma unroll
            for (int s = 0; s < 4; s++) {
                ull qd = dup2(qrow[s * 16]);
                ffma2(acc2[s][0], l0.x, qd); ffma2(acc2[s][1], l0.y, qd);
                ffma2(acc2[s][2], l1.x, qd); ffma2(acc2[s][3], l1.y, qd);
                ffma2(acc2[s][4], l2.x, qd); ffma2(acc2[s][5], l2.y, qd);
                ffma2(acc2[s][6], l3.x, qd); ffma2(acc2[s][7], l3.y, qd);
            }
        }

        // position term (conv folded into r)
#pragma unroll
        for (int dy = 0; dy < 3; dy++) {
#pragma unroll
            for (int s = 0; s < 4; s++) {
                const float* vrow = vt + ((ty + dy) * 66 + pxg + s * 16) * 36 + vh * 16;
#pragma unroll
                for (int dx = 0; dx < 3; dx++) {
                    ulonglong2 va = *(const ulonglong2*)(vrow + dx * 36);
                    ulonglong2 vb2 = *(const ulonglong2*)(vrow + dx * 36 + 4);
                    ulonglong2 vc2 = *(const ulonglong2*)(vrow + dx * 36 + 8);
                    ulonglong2 vd2 = *(const ulonglong2*)(vrow + dx * 36 + 12);
                    ull rd = dup2(r[s][dy * 3 + dx]);
                    ffma2(acc2[s][0], va.x, rd);  ffma2(acc2[s][1], va.y, rd);
                    ffma2(acc2[s][2], vb2.x, rd); ffma2(acc2[s][3], vb2.y, rd);
                    ffma2(acc2[s][4], vc2.x, rd); ffma2(acc2[s][5], vc2.y, rd);
                    ffma2(acc2[s][6], vd2.x, rd); ffma2(acc2[s][7], vd2.y, rd);
                }
            }
        }

        float* ob = out + ((size_t)b * 128 + hd * 32 + vh * 16) * NPIX + (gy + ty) * 256 + gx + pxg;
#pragma unroll
        for (int p = 0; p < 8; p++) {
            float2 s0 = unpk(acc2[0][p]), s1 = unpk(acc2[1][p]);
            float2 s2 = unpk(acc2[2][p]), s3 = unpk(acc2[3][p]);
            float* o0 = ob + (size_t)(2*p) * NPIX;
            o0[0] = s0.x; o0[16] = s1.x; o0[32] = s2.x; o0[48] = s3.x;
            float* o1 = ob + (size_t)(2*p+1) * NPIX;
            o1[0] = s0.y; o1[16] = s1.y; o1[32] = s2.y; o1[48] = s3.y;
        }
    }
}

// ---------------- launch ----------------
extern "C" void kernel_launch(void* const* d_in, const int* in_sizes, int n_in,
                              void* d_out, int out_size) {
    const float* x  = (const float*)d_in[0];
    const float* Wq = (const float*)d_in[1];
    const float* gq = (const float*)d_in[2];
    const float* bq = (const float*)d_in[3];
    const float* Wk = (const float*)d_in[4];
    const float* Wv = (const float*)d_in[5];
    const float* gv = (const float*)d_in[6];
    const float* bv = (const float*)d_in[7];
    const float* Wp = (const float*)d_in[8];
    const float* bp = (const float*)d_in[9];
    float* out = (float*)d_out;

    zero_kernel<<<1, 256>>>();
    qproj_kernel<<<dim3(NPIX / 256, NB), 256>>>(x, Wq, gq, bq);
    kvproj_kernel<<<dim3(NPIX / 256, NB), 192>>>(x, Wk, Wv, gv, bv);
    cross_kernel<<<dim3(32, NB), 512>>>();
    finalize_kernel<<<1, 512>>>(bp);
    out_kernel<<<dim3(4, 128, NB), 128>>>(Wp, out);
}